// round 6
// baseline (speedup 1.0000x reference)
#include <cuda_runtime.h>
#include <cuda_fp16.h>
#include <cstdint>

#define BB   512
#define NN   256
#define NVT  32
#define HS   128
#define G3   384
#define NZ   64

// ---------- device globals (no allocation allowed) ----------
// B fragments: [s(2)][nt(64)][k(2)][lane(32)][reg(2)][half(2)] bf16 = 64 KB
__device__ uint4 g_Bf4[4096];
// gi table, fp16, layout [c(3)][h(128)][t(32)] = 24 KB (b_hh baked into r,z)
__device__ uint4 g_giT4[1536];
// A fragments per batch: [mt(16)][k(2)][lane(32)][reg(4)] bf16x2 = 16 KB/batch
__device__ uint4 g_Af4[(size_t)BB * 1024];

__device__ __forceinline__ float fast_sigmoid(float x) {
    return __fdividef(1.f, 1.f + __expf(-x));
}
__device__ __forceinline__ float tanh_fast(float x) {
    float y;
    asm("tanh.approx.f32 %0, %1;" : "=f"(y) : "f"(x));
    return y;
}
__device__ __forceinline__ uint32_t f2bf(float x) {   // rn bf16 bits
    uint32_t u = __float_as_uint(x);
    u += 0x7fff + ((u >> 16) & 1);
    return u >> 16;
}
__device__ __forceinline__ void mma_bf16(float* c, const uint32_t* a,
                                         uint32_t b0, uint32_t b1) {
    asm volatile(
        "mma.sync.aligned.m16n8k16.row.col.f32.bf16.bf16.f32 "
        "{%0,%1,%2,%3}, {%4,%5,%6,%7}, {%8,%9}, {%0,%1,%2,%3};"
        : "+f"(c[0]), "+f"(c[1]), "+f"(c[2]), "+f"(c[3])
        : "r"(a[0]), "r"(a[1]), "r"(a[2]), "r"(a[3]), "r"(b0), "r"(b1));
}

// ---------- fused kernel: blocks [0,512) histogram, [512,544) tables ----------
__global__ __launch_bounds__(256)
void dvae_hist_tables_kernel(const int* __restrict__ node_types,
                             const int* __restrict__ adj,
                             const float* __restrict__ W_ih,
                             const float* __restrict__ W_hh,
                             const float* __restrict__ b_ih,
                             const float* __restrict__ b_hh,
                             const float* __restrict__ Wg,
                             const float* __restrict__ bg,
                             const float* __restrict__ Wm) {
    __shared__ int   s_cnti[NVT * NN];
    __shared__ int   s_type[NN];
    __shared__ int   s_perm[NN];
    __shared__ int   s_st[NN];
    __shared__ int   s_flushT[NN];
    __shared__ int   s_toff[NVT];
    __shared__ float s_tbl[HS];

    const int tid = threadIdx.x;

    if (blockIdx.x >= BB) {
        // ================= tables block =================
        const int t = blockIdx.x - BB;       // 0..31 (type = K index)
        if (tid < HS) {
            float x  = Wg[tid * NVT + t] + bg[tid];
            float sg = __fdividef(1.f, 1.f + __expf(-x));
            s_tbl[tid] = sg * Wm[tid * NVT + t];
        }
        __syncthreads();

        unsigned short* B = (unsigned short*)g_Bf4;
        auto storeB = [&](int j, float val) {
            int nt = j >> 3, nin = j & 7;
            int k = t >> 4, kk = t & 15;
            int tig = (kk & 7) >> 1, half = kk & 1, reg = kk >> 3;
            int lane = nin * 4 + tig;
            int base = (((nt * 2 + k) * 32 + lane) * 2 + reg) * 2 + half;
            uint32_t hb = f2bf(val);
            float lo = val - __uint_as_float(hb << 16);
            B[base]         = (unsigned short)hb;
            B[16384 + base] = (unsigned short)f2bf(lo);
        };

        for (int g = tid; g < G3; g += 256) {
            const float4* w4 = (const float4*)(W_hh + g * HS);
            const float4* t4 = (const float4*)s_tbl;
            float a0 = 0.f, a1 = 0.f, a2 = 0.f, a3 = 0.f;
            #pragma unroll
            for (int i = 0; i < 32; i += 4) {
                float4 w0 = w4[i], w1 = w4[i+1], w2 = w4[i+2], w3 = w4[i+3];
                float4 x0 = t4[i], x1 = t4[i+1], x2 = t4[i+2], x3 = t4[i+3];
                a0 += w0.x*x0.x + w0.y*x0.y + w0.z*x0.z + w0.w*x0.w;
                a1 += w1.x*x1.x + w1.y*x1.y + w1.z*x1.z + w1.w*x1.w;
                a2 += w2.x*x2.x + w2.y*x2.y + w2.z*x2.z + w2.w*x2.w;
                a3 += w3.x*x3.x + w3.y*x3.y + w3.z*x3.z + w3.w*x3.w;
            }
            float acc = (a0 + a1) + (a2 + a3);
            storeB((g & 127) * 4 + (g >> 7), acc);   // j = h*4 + c
            __half* GI = (__half*)g_giT4;
            int c = g >> 7, h = g & 127;
            float val = W_ih[g * NVT + t] + b_ih[g] + ((g < 256) ? b_hh[g] : 0.f);
            GI[(c * 128 + h) * 32 + t] = __float2half_rn(val);
        }
        if (tid < HS) storeB(tid * 4 + 3, s_tbl[tid]);   // tbl columns
        return;
    }

    // ================= histogram block =================
    const int b = blockIdx.x;
    s_type[tid] = node_types[b * NN + tid];
    for (int i = tid; i < NVT * NN; i += 256) s_cnti[i] = 0;
    __syncthreads();

    // counting-sort u by type
    if (tid < NVT) {
        int c = 0;
        #pragma unroll 8
        for (int u = 0; u < NN; u++) c += (s_type[u] == tid);
        int x = c;
        #pragma unroll
        for (int off = 1; off < 32; off <<= 1) {
            int y = __shfl_up_sync(0xffffffffu, x, off);
            if ((tid & 31) >= off) x += y;
        }
        s_toff[tid] = x - c;      // exclusive prefix
    }
    __syncthreads();
    {
        const int myt = s_type[tid];
        int r = 0;
        #pragma unroll 8
        for (int i = 0; i < NN; i++)
            r += (i < tid) && (s_type[i] == myt);
        s_perm[s_toff[myt] + r] = tid;
    }
    __syncthreads();
    s_st[tid] = s_type[s_perm[tid]];
    __syncthreads();
    s_flushT[tid] = (tid == NN - 1 || s_st[tid + 1] != s_st[tid])
                    ? (s_st[tid] + 1) : 0;
    __syncthreads();

    // run-accumulation: 1 LDG + 1 IADD per u, rare predicated flush
    {
        const int* col = adj + (size_t)b * NN * NN + tid;
        int acc = 0;
        #pragma unroll 8
        for (int j = 0; j < NN; j++) {
            int u = s_perm[j];                 // broadcast LDS
            acc += __ldg(col + u * NN);
            int f = s_flushT[j];               // broadcast LDS
            if (f) { s_cnti[(f - 1) * NN + tid] = acc; acc = 0; }
        }
    }
    __syncthreads();

    // write A fragments: counts are exact in bf16 (<= 255)
    uint32_t* dst = (uint32_t*)g_Af4 + (size_t)b * 4096;
    for (int lin = tid; lin < 4096; lin += 256) {
        int reg  = lin & 3;
        int lane = (lin >> 2) & 31;
        int k    = (lin >> 7) & 1;
        int mt   = lin >> 8;
        int g    = lane >> 2, tig = lane & 3;
        int v    = mt * 16 + (reg & 1) * 8 + g;
        int t0   = k * 16 + (reg >> 1) * 8 + tig * 2;
        uint32_t u0 = __float_as_uint((float)s_cnti[t0 * NN + v]) >> 16;
        uint32_t u1 = __float_as_uint((float)s_cnti[(t0 + 1) * NN + v]) >> 16;
        dst[lin] = u0 | (u1 << 16);
    }
}

// ---------- main kernel: bf16 mma GEMM + GRU + heads ----------
// smem: sB 64K + pgi 24K + pbhn 512 + spart 4096 + phg 512 = 93.0 KB
#define SMEM_DYN (65536 + 24576 + 512 + 4096 + 512)

__global__ __launch_bounds__(256, 2)
void dvae_main_kernel(const int* __restrict__ node_types,
                      const float* __restrict__ b_hh,
                      const float* __restrict__ W1, const float* __restrict__ b1,
                      const float* __restrict__ W2, const float* __restrict__ b2,
                      float* __restrict__ out) {
    extern __shared__ char smem[];
    uint32_t* sB    = (uint32_t*)smem;                  // 16384 u32
    __half*   pgi   = (__half*)(smem + 65536);          // 12288 halves
    float*    pbhn  = (float*)(smem + 65536 + 24576);   // [128]
    float*    spart = pbhn + 128;                       // [8][128]
    float*    phg   = spart + 8 * 128;                  // [128]

    const int b    = blockIdx.x;
    const int tid  = threadIdx.x;
    const int wid  = tid >> 5;
    const int lane = tid & 31;

    // ---- stage B frags + gi (uint4 copies) ----
    {
        uint4* d = (uint4*)sB;
        for (int i = tid; i < 4096; i += 256) d[i] = g_Bf4[i];
        uint4* d2 = (uint4*)pgi;
        for (int i = tid; i < 1536; i += 256) d2[i] = g_giT4[i];
    }
    if (tid < 128) pbhn[tid] = b_hh[256 + tid];
    __syncthreads();

    // ---- A fragments: 2 m-tiles per warp, 2 k-steps ----
    uint4 areg[2][2];
    #pragma unroll
    for (int mt2 = 0; mt2 < 2; mt2++)
        #pragma unroll
        for (int k = 0; k < 2; k++)
            areg[mt2][k] = g_Af4[(size_t)b * 1024 +
                                 (((wid * 2 + mt2) * 2 + k) * 32 + lane)];

    const int g    = lane >> 2;
    const int tig  = lane & 3;
    const int odd  = tig & 1;
    const int hbit = tig >> 1;
    const int rowoff = g + (odd << 3);

    int   tv[2];
    bool  excl[2];
    #pragma unroll
    for (int mt2 = 0; mt2 < 2; mt2++) {
        int v = (wid * 2 + mt2) * 16 + rowoff;
        tv[mt2]   = node_types[b * NN + v];
        excl[mt2] = (v == 0) || (v == NN - 1);
    }

    // ---- GEMM + fused epilogue over 64 n-tiles ----
    #pragma unroll 2
    for (int nt = 0; nt < 64; nt++) {
        float cc[2][4] = {{0.f,0.f,0.f,0.f},{0.f,0.f,0.f,0.f}};
        #pragma unroll
        for (int s = 0; s < 2; s++)
            #pragma unroll
            for (int k = 0; k < 2; k++) {
                uint2 bb = *(const uint2*)(sB +
                    (((s * 64 + nt) * 2 + k) * 32 + lane) * 2);
                mma_bf16(cc[0], (const uint32_t*)&areg[0][k], bb.x, bb.y);
                mma_bf16(cc[1], (const uint32_t*)&areg[1][k], bb.x, bb.y);
            }

        const int h = nt * 2 + hbit;
        const float bhn = pbhn[h];
        float acc = 0.f;
        #pragma unroll
        for (int mt2 = 0; mt2 < 2; mt2++) {
            float* c = cc[mt2];
            // exchange between (r,z) lanes and (n,tb) lanes
            float r1 = __shfl_xor_sync(0xffffffffu, odd ? c[0] : c[2], 1);
            float r2 = __shfl_xor_sync(0xffffffffu, odd ? c[1] : c[3], 1);
            float rin  = odd ? r1 : c[0];
            float zin  = odd ? r2 : c[1];
            float nin  = odd ? c[2] : r1;
            float hpre = odd ? c[3] : r2;
            int ti = tv[mt2];
            float gi_r = __half2float(pgi[(      h) * 32 + ti]);
            float gi_z = __half2float(pgi[(128 + h) * 32 + ti]);
            float gi_n = __half2float(pgi[(256 + h) * 32 + ti]);
            float r  = fmaf(tanh_fast(0.5f * (gi_r + rin)), 0.5f, 0.5f);
            float z  = fast_sigmoid(gi_z + zin);          // exact: scales Hpre
            float nn = tanh_fast(gi_n + r * (nin + bhn));
            float Hv = (1.f - z) * nn + z * hpre;
            if (!excl[mt2]) acc += Hv;
        }
        // reduce the 16 lanes sharing this h (masks avoid bit 1<<1)
        acc += __shfl_xor_sync(0xffffffffu, acc, 1);
        acc += __shfl_xor_sync(0xffffffffu, acc, 4);
        acc += __shfl_xor_sync(0xffffffffu, acc, 8);
        acc += __shfl_xor_sync(0xffffffffu, acc, 16);
        if ((lane & ~2u) == 0)            // lanes 0 (h even) and 2 (h odd)
            spart[wid * 128 + nt * 2 + (lane >> 1)] = acc;
    }
    __syncthreads();

    // ---- reduce partials, heads ----
    if (tid < HS) {
        float s = 0.f;
        #pragma unroll
        for (int w = 0; w < 8; w++) s += spart[w * 128 + tid];
        phg[tid] = s;
    }
    __syncthreads();

    if (tid < 2 * NZ) {
        const int j = tid & (NZ - 1);
        const float* W  = (tid < NZ) ? W1 : W2;
        const float* bv = (tid < NZ) ? b1 : b2;
        float a0 = bv[j], a1 = 0.f, a2 = 0.f, a3 = 0.f;
        #pragma unroll
        for (int h = 0; h < HS; h += 4) {
            a0 += phg[h + 0] * W[j * HS + h + 0];
            a1 += phg[h + 1] * W[j * HS + h + 1];
            a2 += phg[h + 2] * W[j * HS + h + 2];
            a3 += phg[h + 3] * W[j * HS + h + 3];
        }
        out[((tid < NZ) ? 0 : BB * NZ) + b * NZ + j] = (a0 + a1) + (a2 + a3);
    }
}

// ---------- launch ----------
extern "C" void kernel_launch(void* const* d_in, const int* in_sizes, int n_in,
                              void* d_out, int out_size) {
    const int*   node_types = (const int*)  d_in[0];
    const int*   adj        = (const int*)  d_in[1];
    const float* W_ih       = (const float*)d_in[2];
    const float* W_hh       = (const float*)d_in[3];
    const float* b_ih       = (const float*)d_in[4];
    const float* b_hh       = (const float*)d_in[5];
    const float* Wg         = (const float*)d_in[6];
    const float* bg         = (const float*)d_in[7];
    const float* Wm         = (const float*)d_in[8];
    const float* W1         = (const float*)d_in[9];
    const float* b1         = (const float*)d_in[10];
    const float* W2         = (const float*)d_in[11];
    const float* b2         = (const float*)d_in[12];
    float* out = (float*)d_out;

    cudaFuncSetAttribute(dvae_main_kernel,
                         cudaFuncAttributeMaxDynamicSharedMemorySize, SMEM_DYN);

    dvae_hist_tables_kernel<<<BB + NVT, 256>>>(node_types, adj,
                                               W_ih, W_hh, b_ih, b_hh,
                                               Wg, bg, Wm);
    dvae_main_kernel<<<BB, 256, SMEM_DYN>>>(node_types, b_hh,
                                            W1, b1, W2, b2, out);
}

// round 7
// speedup vs baseline: 2.6589x; 2.6589x over previous
#include <cuda_runtime.h>
#include <cuda_fp16.h>
#include <cstdint>

#define BB   512
#define NN   256
#define NVT  32
#define HS   128
#define G3   384
#define NZ   64

// ---------- device globals (no allocation allowed) ----------
// B fragments: [s(2)][nt(64)][k(2)][lane(32)][reg(2)][half(2)] bf16 = 64 KB
__device__ uint4 g_Bf4[4096];
// gi table, fp16, layout [c(3)][h(128)][t(32)] = 24 KB (b_hh baked into r,z)
__device__ uint4 g_giT4[1536];
// A fragments per batch: [mt(16)][k(2)][lane(32)][reg(4)] bf16x2 = 16 KB/batch
__device__ uint4 g_Af4[(size_t)BB * 1024];

__device__ __forceinline__ float fast_sigmoid(float x) {
    return __fdividef(1.f, 1.f + __expf(-x));
}
__device__ __forceinline__ float tanh_fast(float x) {
    float y;
    asm("tanh.approx.f32 %0, %1;" : "=f"(y) : "f"(x));
    return y;
}
__device__ __forceinline__ uint32_t f2bf(float x) {   // rn bf16 bits
    uint32_t u = __float_as_uint(x);
    u += 0x7fff + ((u >> 16) & 1);
    return u >> 16;
}
__device__ __forceinline__ void mma_bf16(float* c, const uint32_t* a,
                                         uint32_t b0, uint32_t b1) {
    asm volatile(
        "mma.sync.aligned.m16n8k16.row.col.f32.bf16.bf16.f32 "
        "{%0,%1,%2,%3}, {%4,%5,%6,%7}, {%8,%9}, {%0,%1,%2,%3};"
        : "+f"(c[0]), "+f"(c[1]), "+f"(c[2]), "+f"(c[3])
        : "r"(a[0]), "r"(a[1]), "r"(a[2]), "r"(a[3]), "r"(b0), "r"(b1));
}

// ---------- fused kernel: blocks [0,512) histogram, [512,544) tables ----------
__global__ __launch_bounds__(256)
void dvae_hist_tables_kernel(const int* __restrict__ node_types,
                             const int* __restrict__ adj,
                             const float* __restrict__ W_ih,
                             const float* __restrict__ W_hh,
                             const float* __restrict__ b_ih,
                             const float* __restrict__ b_hh,
                             const float* __restrict__ Wg,
                             const float* __restrict__ bg,
                             const float* __restrict__ Wm) {
    __shared__ int   s_cnti[NVT * NN];
    __shared__ int   s_type[NN];
    __shared__ int   s_perm[NN];
    __shared__ int   s_st[NN];
    __shared__ int   s_flushT[NN];
    __shared__ int   s_toff[NVT];
    __shared__ float s_tbl[HS];

    const int tid = threadIdx.x;

    if (blockIdx.x >= BB) {
        // ================= tables block =================
        const int t = blockIdx.x - BB;       // 0..31 (type = K index)
        if (tid < HS) {
            float x  = Wg[tid * NVT + t] + bg[tid];
            float sg = __fdividef(1.f, 1.f + __expf(-x));
            s_tbl[tid] = sg * Wm[tid * NVT + t];
        }
        __syncthreads();

        unsigned short* B = (unsigned short*)g_Bf4;
        auto storeB = [&](int j, float val) {
            int nt = j >> 3, nin = j & 7;
            int k = t >> 4, kk = t & 15;
            int tig = (kk & 7) >> 1, half = kk & 1, reg = kk >> 3;
            int lane = nin * 4 + tig;
            int base = (((nt * 2 + k) * 32 + lane) * 2 + reg) * 2 + half;
            uint32_t hb = f2bf(val);
            float lo = val - __uint_as_float(hb << 16);
            B[base]         = (unsigned short)hb;
            B[16384 + base] = (unsigned short)f2bf(lo);
        };

        for (int g = tid; g < G3; g += 256) {
            const float4* w4 = (const float4*)(W_hh + g * HS);
            const float4* t4 = (const float4*)s_tbl;
            float a0 = 0.f, a1 = 0.f, a2 = 0.f, a3 = 0.f;
            #pragma unroll
            for (int i = 0; i < 32; i += 4) {
                float4 w0 = w4[i], w1 = w4[i+1], w2 = w4[i+2], w3 = w4[i+3];
                float4 x0 = t4[i], x1 = t4[i+1], x2 = t4[i+2], x3 = t4[i+3];
                a0 += w0.x*x0.x + w0.y*x0.y + w0.z*x0.z + w0.w*x0.w;
                a1 += w1.x*x1.x + w1.y*x1.y + w1.z*x1.z + w1.w*x1.w;
                a2 += w2.x*x2.x + w2.y*x2.y + w2.z*x2.z + w2.w*x2.w;
                a3 += w3.x*x3.x + w3.y*x3.y + w3.z*x3.z + w3.w*x3.w;
            }
            float acc = (a0 + a1) + (a2 + a3);
            storeB((g & 127) * 4 + (g >> 7), acc);   // j = h*4 + c
            __half* GI = (__half*)g_giT4;
            int c = g >> 7, h = g & 127;
            float val = W_ih[g * NVT + t] + b_ih[g] + ((g < 256) ? b_hh[g] : 0.f);
            GI[(c * 128 + h) * 32 + t] = __float2half_rn(val);
        }
        if (tid < HS) storeB(tid * 4 + 3, s_tbl[tid]);   // tbl columns
        return;
    }

    // ================= histogram block =================
    const int b = blockIdx.x;
    s_type[tid] = node_types[b * NN + tid];
    for (int i = tid; i < NVT * NN; i += 256) s_cnti[i] = 0;
    __syncthreads();

    // counting-sort u by type
    if (tid < NVT) {
        int c = 0;
        #pragma unroll 8
        for (int u = 0; u < NN; u++) c += (s_type[u] == tid);
        int x = c;
        #pragma unroll
        for (int off = 1; off < 32; off <<= 1) {
            int y = __shfl_up_sync(0xffffffffu, x, off);
            if ((tid & 31) >= off) x += y;
        }
        s_toff[tid] = x - c;      // exclusive prefix
    }
    __syncthreads();
    {
        const int myt = s_type[tid];
        int r = 0;
        #pragma unroll 8
        for (int i = 0; i < NN; i++)
            r += (i < tid) && (s_type[i] == myt);
        s_perm[s_toff[myt] + r] = tid;
    }
    __syncthreads();
    s_st[tid] = s_type[s_perm[tid]];
    __syncthreads();
    s_flushT[tid] = (tid == NN - 1 || s_st[tid + 1] != s_st[tid])
                    ? (s_st[tid] + 1) : 0;
    __syncthreads();

    // run-accumulation with EXPLICIT 8-wide load batching (MLP=8):
    // all 8 LDGs issue before any add/flush touches them.
    {
        const int* col = adj + (size_t)b * NN * NN + tid;
        int acc = 0;
        #pragma unroll 1
        for (int j0 = 0; j0 < NN; j0 += 8) {
            int u0 = s_perm[j0 + 0], u1 = s_perm[j0 + 1];
            int u2 = s_perm[j0 + 2], u3 = s_perm[j0 + 3];
            int u4 = s_perm[j0 + 4], u5 = s_perm[j0 + 5];
            int u6 = s_perm[j0 + 6], u7 = s_perm[j0 + 7];
            int a0 = __ldg(col + u0 * NN);
            int a1 = __ldg(col + u1 * NN);
            int a2 = __ldg(col + u2 * NN);
            int a3 = __ldg(col + u3 * NN);
            int a4 = __ldg(col + u4 * NN);
            int a5 = __ldg(col + u5 * NN);
            int a6 = __ldg(col + u6 * NN);
            int a7 = __ldg(col + u7 * NN);
            int f0 = s_flushT[j0 + 0], f1 = s_flushT[j0 + 1];
            int f2 = s_flushT[j0 + 2], f3 = s_flushT[j0 + 3];
            int f4 = s_flushT[j0 + 4], f5 = s_flushT[j0 + 5];
            int f6 = s_flushT[j0 + 6], f7 = s_flushT[j0 + 7];
            acc += a0; if (f0) { s_cnti[(f0 - 1) * NN + tid] = acc; acc = 0; }
            acc += a1; if (f1) { s_cnti[(f1 - 1) * NN + tid] = acc; acc = 0; }
            acc += a2; if (f2) { s_cnti[(f2 - 1) * NN + tid] = acc; acc = 0; }
            acc += a3; if (f3) { s_cnti[(f3 - 1) * NN + tid] = acc; acc = 0; }
            acc += a4; if (f4) { s_cnti[(f4 - 1) * NN + tid] = acc; acc = 0; }
            acc += a5; if (f5) { s_cnti[(f5 - 1) * NN + tid] = acc; acc = 0; }
            acc += a6; if (f6) { s_cnti[(f6 - 1) * NN + tid] = acc; acc = 0; }
            acc += a7; if (f7) { s_cnti[(f7 - 1) * NN + tid] = acc; acc = 0; }
        }
    }
    __syncthreads();

    // write A fragments: counts are exact in bf16 (<= 255)
    uint32_t* dst = (uint32_t*)g_Af4 + (size_t)b * 4096;
    for (int lin = tid; lin < 4096; lin += 256) {
        int reg  = lin & 3;
        int lane = (lin >> 2) & 31;
        int k    = (lin >> 7) & 1;
        int mt   = lin >> 8;
        int g    = lane >> 2, tig = lane & 3;
        int v    = mt * 16 + (reg & 1) * 8 + g;
        int t0   = k * 16 + (reg >> 1) * 8 + tig * 2;
        uint32_t u0 = __float_as_uint((float)s_cnti[t0 * NN + v]) >> 16;
        uint32_t u1 = __float_as_uint((float)s_cnti[(t0 + 1) * NN + v]) >> 16;
        dst[lin] = u0 | (u1 << 16);
    }
}

// ---------- main kernel: bf16 mma GEMM + GRU + heads ----------
// smem: sB 64K + spart 4K + phg 512 = 69.0 KB -> 3 CTAs/SM
#define SMEM_DYN (65536 + 4096 + 512)

__global__ __launch_bounds__(256, 3)
void dvae_main_kernel(const int* __restrict__ node_types,
                      const float* __restrict__ b_hh,
                      const float* __restrict__ W1, const float* __restrict__ b1,
                      const float* __restrict__ W2, const float* __restrict__ b2,
                      float* __restrict__ out) {
    extern __shared__ char smem[];
    uint32_t* sB    = (uint32_t*)smem;                  // 16384 u32
    float*    spart = (float*)(smem + 65536);           // [8][128]
    float*    phg   = spart + 8 * 128;                  // [128]

    const int b    = blockIdx.x;
    const int tid  = threadIdx.x;
    const int wid  = tid >> 5;
    const int lane = tid & 31;
    const __half* GI = (const __half*)g_giT4;

    // ---- stage B frags (uint4 copies) ----
    {
        uint4* d = (uint4*)sB;
        for (int i = tid; i < 4096; i += 256) d[i] = g_Bf4[i];
    }
    __syncthreads();

    // ---- A fragments: 2 m-tiles per warp, 2 k-steps ----
    uint4 areg[2][2];
    #pragma unroll
    for (int mt2 = 0; mt2 < 2; mt2++)
        #pragma unroll
        for (int k = 0; k < 2; k++)
            areg[mt2][k] = g_Af4[(size_t)b * 1024 +
                                 (((wid * 2 + mt2) * 2 + k) * 32 + lane)];

    const int g    = lane >> 2;
    const int tig  = lane & 3;
    const int odd  = tig & 1;
    const int hbit = tig >> 1;
    const int rowoff = g + (odd << 3);

    int   tv[2];
    bool  excl[2];
    #pragma unroll
    for (int mt2 = 0; mt2 < 2; mt2++) {
        int v = (wid * 2 + mt2) * 16 + rowoff;
        tv[mt2]   = node_types[b * NN + v];
        excl[mt2] = (v == 0) || (v == NN - 1);
    }

    // ---- GEMM + fused epilogue over 64 n-tiles ----
    #pragma unroll 2
    for (int nt = 0; nt < 64; nt++) {
        float cc[2][4] = {{0.f,0.f,0.f,0.f},{0.f,0.f,0.f,0.f}};
        #pragma unroll
        for (int s = 0; s < 2; s++)
            #pragma unroll
            for (int k = 0; k < 2; k++) {
                uint2 bb = *(const uint2*)(sB +
                    (((s * 64 + nt) * 2 + k) * 32 + lane) * 2);
                mma_bf16(cc[0], (const uint32_t*)&areg[0][k], bb.x, bb.y);
                mma_bf16(cc[1], (const uint32_t*)&areg[1][k], bb.x, bb.y);
            }

        const int h = nt * 2 + hbit;
        const float bhn = __ldg(b_hh + 256 + h);
        float acc = 0.f;
        #pragma unroll
        for (int mt2 = 0; mt2 < 2; mt2++) {
            float* c = cc[mt2];
            // exchange between (r,z) lanes and (n,tb) lanes
            float r1 = __shfl_xor_sync(0xffffffffu, odd ? c[0] : c[2], 1);
            float r2 = __shfl_xor_sync(0xffffffffu, odd ? c[1] : c[3], 1);
            float rin  = odd ? r1 : c[0];
            float zin  = odd ? r2 : c[1];
            float nin  = odd ? c[2] : r1;
            float hpre = odd ? c[3] : r2;
            int ti = tv[mt2];
            float gi_r = __half2float(__ldg(GI + (      h) * 32 + ti));
            float gi_z = __half2float(__ldg(GI + (128 + h) * 32 + ti));
            float gi_n = __half2float(__ldg(GI + (256 + h) * 32 + ti));
            float r  = fmaf(tanh_fast(0.5f * (gi_r + rin)), 0.5f, 0.5f);
            float z  = fast_sigmoid(gi_z + zin);          // exact: scales Hpre
            float nn = tanh_fast(gi_n + r * (nin + bhn));
            float Hv = (1.f - z) * nn + z * hpre;
            if (!excl[mt2]) acc += Hv;
        }
        // reduce the 16 lanes sharing this h (masks avoid bit 1<<1)
        acc += __shfl_xor_sync(0xffffffffu, acc, 1);
        acc += __shfl_xor_sync(0xffffffffu, acc, 4);
        acc += __shfl_xor_sync(0xffffffffu, acc, 8);
        acc += __shfl_xor_sync(0xffffffffu, acc, 16);
        if ((lane & ~2u) == 0)            // lanes 0 (h even) and 2 (h odd)
            spart[wid * 128 + nt * 2 + (lane >> 1)] = acc;
    }
    __syncthreads();

    // ---- reduce partials, heads ----
    if (tid < HS) {
        float s = 0.f;
        #pragma unroll
        for (int w = 0; w < 8; w++) s += spart[w * 128 + tid];
        phg[tid] = s;
    }
    __syncthreads();

    if (tid < 2 * NZ) {
        const int j = tid & (NZ - 1);
        const float* W  = (tid < NZ) ? W1 : W2;
        const float* bv = (tid < NZ) ? b1 : b2;
        float a0 = bv[j], a1 = 0.f, a2 = 0.f, a3 = 0.f;
        #pragma unroll
        for (int h = 0; h < HS; h += 4) {
            a0 += phg[h + 0] * W[j * HS + h + 0];
            a1 += phg[h + 1] * W[j * HS + h + 1];
            a2 += phg[h + 2] * W[j * HS + h + 2];
            a3 += phg[h + 3] * W[j * HS + h + 3];
        }
        out[((tid < NZ) ? 0 : BB * NZ) + b * NZ + j] = (a0 + a1) + (a2 + a3);
    }
}

// ---------- launch ----------
extern "C" void kernel_launch(void* const* d_in, const int* in_sizes, int n_in,
                              void* d_out, int out_size) {
    const int*   node_types = (const int*)  d_in[0];
    const int*   adj        = (const int*)  d_in[1];
    const float* W_ih       = (const float*)d_in[2];
    const float* W_hh       = (const float*)d_in[3];
    const float* b_ih       = (const float*)d_in[4];
    const float* b_hh       = (const float*)d_in[5];
    const float* Wg         = (const float*)d_in[6];
    const float* bg         = (const float*)d_in[7];
    const float* Wm         = (const float*)d_in[8];
    const float* W1         = (const float*)d_in[9];
    const float* b1         = (const float*)d_in[10];
    const float* W2         = (const float*)d_in[11];
    const float* b2         = (const float*)d_in[12];
    float* out = (float*)d_out;

    cudaFuncSetAttribute(dvae_main_kernel,
                         cudaFuncAttributeMaxDynamicSharedMemorySize, SMEM_DYN);

    dvae_hist_tables_kernel<<<BB + NVT, 256>>>(node_types, adj,
                                               W_ih, W_hh, b_ih, b_hh,
                                               Wg, bg, Wm);
    dvae_main_kernel<<<BB, 256, SMEM_DYN>>>(node_types, b_hh,
                                            W1, b1, W2, b2, out);
}